// round 8
// baseline (speedup 1.0000x reference)
#include <cuda_runtime.h>

#define BB   64
#define TT   512
#define DD   256
#define HH   256
#define G4   (4*HH)
#define NBLK 128
#define NTHR 256
#define NBG  4      // batch groups (16 batches each)
#define NUG  32     // unit groups (8 units each)
#define BPB  16     // batches per block
#define UPB  8      // units per block

// h after each step: g_h[t][b][unit]
__device__ float g_h[TT][BB][HH];
// per-step, per-batch-group arrival counters (target = NUG)
__device__ unsigned g_cnt[TT][NBG];

typedef unsigned long long u64;

// ---------------------------------------------------------------------------
__global__ void init_kernel() {
    int i = blockIdx.x * blockDim.x + threadIdx.x;
    if (i < TT * NBG) ((unsigned*)g_cnt)[i] = 0u;
}

// ---------------------------------------------------------------------------
__device__ __forceinline__ float sigm(float x) {
    x = fminf(fmaxf(x, -30.f), 30.f);
    return 1.0f / (1.0f + __expf(-x));
}
__device__ __forceinline__ float tanh_e(float x) {
    x = fminf(fmaxf(x, -15.f), 15.f);
    float e = __expf(2.0f * x);
    return (e - 1.0f) / (e + 1.0f);
}

// packed fp32x2 FMA (sm_103a FFMA2 — 2x fp32 throughput per issue)
__device__ __forceinline__ u64 ffma2(u64 a, u64 b, u64 c) {
    u64 d;
    asm("fma.rn.f32x2 %0, %1, %2, %3;" : "=l"(d) : "l"(a), "l"(b), "l"(c));
    return d;
}
__device__ __forceinline__ u64 pack2(float lo, float hi) {
    u64 d; asm("mov.b64 %0, {%1, %2};" : "=l"(d) : "f"(lo), "f"(hi)); return d;
}
__device__ __forceinline__ float2 unpack2(u64 v) {
    float lo, hi; asm("mov.b64 {%0, %1}, %2;" : "=f"(lo), "=f"(hi) : "l"(v));
    return make_float2(lo, hi);
}

__device__ __forceinline__ void cp16(void* smem_dst, const void* gsrc) {
    unsigned d = (unsigned)__cvta_generic_to_shared(smem_dst);
    asm volatile("cp.async.cg.shared.global [%0], [%1], 16;" :: "r"(d), "l"(gsrc));
}
__device__ __forceinline__ void cp_commit() { asm volatile("cp.async.commit_group;"); }
__device__ __forceinline__ void cp_wait0()  { asm volatile("cp.async.wait_group 0;"); }

// ---------------------------------------------------------------------------
// Persistent LSTM scan, weights-in-registers.
// Block (bg, ug): batches [bg*16,+16), units [ug*8,+8) -> 32 gate columns.
// Thread tid = c*8 + ks : c = gate*8 + u (column), ks = k-segment (32 k each).
// Holds Wi/Wh[gcol][ks*32..+32] as 16+16 packed u64 registers for the whole
// kernel. Per step: 16 batch-partial dot products (FFMA2), 8-lane shfl
// reduction over ks, activations on threads <128 (one (u,b) each).
__global__ void __launch_bounds__(NTHR, 1) lstm_scan_kernel(
    const float* __restrict__ x,   // [B,T,D]
    const float* __restrict__ Wi,  // [D,4H]
    const float* __restrict__ Wh,  // [H,4H]
    const float* __restrict__ bias)// [4H]
{
    __shared__ __align__(16) float xs[2][BPB][DD];   // 32 KB (double-buffered x tile)
    __shared__ __align__(16) float hs[BPB][HH];      // 16 KB (h_{t-1} tile)
    __shared__ __align__(16) float ps[32][BPB];      //  2 KB (reduced gate sums)

    const int tid = threadIdx.x;
    const int blk = blockIdx.x;
    const int bg  = blk & (NBG - 1);
    const int ug  = blk >> 2;
    const int c   = tid >> 3;          // column 0..31
    const int ks  = tid & 7;           // k-segment 0..7
    const int gate = c >> 3, uu = c & 7;
    const int gcol = gate * HH + ug * UPB + uu;

    // ---- weights into registers (one time) ----
    u64 wi_r[16], wh_r[16];
    #pragma unroll
    for (int j = 0; j < 16; ++j) {
        int k = ks * 32 + 2 * j;
        wi_r[j] = pack2(Wi[(size_t)k * G4 + gcol], Wi[(size_t)(k + 1) * G4 + gcol]);
        wh_r[j] = pack2(Wh[(size_t)k * G4 + gcol], Wh[(size_t)(k + 1) * G4 + gcol]);
    }
    const float bias_c = bias[gcol];

    // activation-state mapping (threads < 128): one (unit, batch) each
    const int au = tid >> 4;           // unit 0..7
    const int ab = tid & 15;           // batch 0..15
    float cst = 0.f;

    // ---- prologue: stage x_0 ----
    #pragma unroll
    for (int j = 0; j < 4; ++j) {
        int chunk = tid + j * NTHR;            // 1024 x 16B chunks
        int bl = chunk >> 6, off = chunk & 63;
        cp16(&xs[0][bl][off * 4],
             x + ((size_t)(bg * BPB + bl) * TT + 0) * DD + off * 4);
    }
    cp_commit(); cp_wait0();
    __syncthreads();

    for (int t = 0; t < TT; ++t) {
        const int cur = t & 1, nxt = cur ^ 1;

        // 1. prefetch x_{t+1} (issued now, committed with the h stage below)
        if (t + 1 < TT) {
            #pragma unroll
            for (int j = 0; j < 4; ++j) {
                int chunk = tid + j * NTHR;
                int bl = chunk >> 6, off = chunk & 63;
                cp16(&xs[nxt][bl][off * 4],
                     x + ((size_t)(bg * BPB + bl) * TT + (t + 1)) * DD + off * 4);
            }
        }

        // 2. x-phase: acc[b] += x_t[b,k] * Wi[k,col]   (16 independent chains)
        u64 acc[BPB];
        #pragma unroll
        for (int b = 0; b < BPB; ++b) acc[b] = 0ull;
        #pragma unroll
        for (int b = 0; b < BPB; ++b) {
            const ulonglong2* xr = (const ulonglong2*)&xs[cur][b][ks * 32];
            #pragma unroll
            for (int i = 0; i < 8; ++i) {
                ulonglong2 xv = xr[i];
                acc[b] = ffma2(wi_r[2 * i],     xv.x, acc[b]);
                acc[b] = ffma2(wi_r[2 * i + 1], xv.y, acc[b]);
            }
        }

        if (t > 0) {
            // 3. wait for all unit-groups of this batch-group at t-1
            if (tid == 0) {
                volatile unsigned* f = &g_cnt[t - 1][bg];
                while (*f < (unsigned)NUG) { }
                __threadfence();               // acquire
            }
            __syncthreads();

            // 4. stage h_{t-1} tile (16 KB contiguous) + retire x prefetch
            const float* hsrc = &g_h[t - 1][bg * BPB][0];
            #pragma unroll
            for (int j = 0; j < 4; ++j) {
                int chunk = tid + j * NTHR;
                cp16((float*)hs + chunk * 4, hsrc + chunk * 4);
            }
            cp_commit(); cp_wait0();
            __syncthreads();

            // 5. h-phase: acc[b] += h_{t-1}[b,k] * Wh[k,col]
            #pragma unroll
            for (int b = 0; b < BPB; ++b) {
                const ulonglong2* hr = (const ulonglong2*)&hs[b][ks * 32];
                #pragma unroll
                for (int i = 0; i < 8; ++i) {
                    ulonglong2 hv = hr[i];
                    acc[b] = ffma2(wh_r[2 * i],     hv.x, acc[b]);
                    acc[b] = ffma2(wh_r[2 * i + 1], hv.y, acc[b]);
                }
            }
        } else {
            cp_commit(); cp_wait0();           // retire x_1 prefetch group
            __syncthreads();
        }

        // 6. reduce over the 8 k-segments (8 consecutive lanes share a column)
        float4 s[4];
        #pragma unroll
        for (int q = 0; q < BPB; ++q) {
            float2 p = unpack2(acc[q]);
            float v = p.x + p.y;
            v += __shfl_xor_sync(0xffffffffu, v, 1);
            v += __shfl_xor_sync(0xffffffffu, v, 2);
            v += __shfl_xor_sync(0xffffffffu, v, 4);
            ((float*)s)[q] = v + bias_c;
        }
        if (ks == 0) {
            float4* pr = (float4*)&ps[c][0];
            pr[0] = s[0]; pr[1] = s[1]; pr[2] = s[2]; pr[3] = s[3];
        }
        __syncthreads();

        // 7. activations: thread (u, b) owns one cell state
        if (tid < 128) {
            float gi = ps[     au][ab];
            float gf = ps[ 8 + au][ab];
            float gg = ps[16 + au][ab];
            float go = ps[24 + au][ab];
            cst = sigm(gf) * cst + sigm(gi) * tanh_e(gg);
            float hv = sigm(go) * tanh_e(cst);
            g_h[t][bg * BPB + ab][ug * UPB + au] = hv;
        }
        __syncthreads();

        // 8. publish
        if (tid == 0) {
            __threadfence();                   // release
            atomicAdd(&g_cnt[t][bg], 1u);
        }
    }
}

// ---------------------------------------------------------------------------
// block-level reductions (256 threads)
__device__ __forceinline__ float block_sum(float v, volatile float* red) {
    int lane = threadIdx.x & 31, wid = threadIdx.x >> 5;
    #pragma unroll
    for (int o = 16; o; o >>= 1) v += __shfl_down_sync(0xffffffffu, v, o);
    if (lane == 0) red[wid] = v;
    __syncthreads();
    if (threadIdx.x == 0) {
        float s = 0.f;
        #pragma unroll
        for (int i = 0; i < 8; ++i) s += red[i];
        red[0] = s;
    }
    __syncthreads();
    float r = red[0];
    __syncthreads();
    return r;
}
__device__ __forceinline__ float block_max(float v, volatile float* red) {
    int lane = threadIdx.x & 31, wid = threadIdx.x >> 5;
    #pragma unroll
    for (int o = 16; o; o >>= 1) v = fmaxf(v, __shfl_down_sync(0xffffffffu, v, o));
    if (lane == 0) red[wid] = v;
    __syncthreads();
    if (threadIdx.x == 0) {
        float s = red[0];
        #pragma unroll
        for (int i = 1; i < 8; ++i) s = fmaxf(s, red[i]);
        red[0] = s;
    }
    __syncthreads();
    float r = red[0];
    __syncthreads();
    return r;
}

// ---------------------------------------------------------------------------
// Attention + MLP tail. One block per batch element.
//   scores_t = scale*((q0 Wk^T)·h_t + q0·bk) ; o0 = (Σ attn_t h_t) Wv + bv
__global__ void __launch_bounds__(NTHR) attn_tail_kernel(
    const float* __restrict__ Wq, const float* __restrict__ bq,
    const float* __restrict__ Wk, const float* __restrict__ bk,
    const float* __restrict__ Wv, const float* __restrict__ bv,
    const float* __restrict__ Wo, const float* __restrict__ bo,
    const float* __restrict__ W1, const float* __restrict__ b1,
    const float* __restrict__ W2, const float* __restrict__ b2,
    float* __restrict__ out)
{
    __shared__ float h0[HH], q0[HH], u[HH], hbar[HH], vb[HH], ob[HH];
    __shared__ float sc[TT];
    __shared__ float z[32];
    __shared__ float red[8];
    __shared__ float qbk_s;

    const int b = blockIdx.x;
    const int tid = threadIdx.x;
    const int lane = tid & 31, wid = tid >> 5;

    h0[tid] = g_h[0][b][tid];
    __syncthreads();

    // q0 = h0 @ Wq + bq
    {
        float s = bq[tid];
        #pragma unroll 4
        for (int d = 0; d < HH; ++d) s = fmaf(h0[d], Wq[d * HH + tid], s);
        q0[tid] = s;
    }
    __syncthreads();

    // qbk = q0 . bk
    {
        float p = q0[tid] * bk[tid];
        float s = block_sum(p, red);
        if (tid == 0) qbk_s = s;
    }
    __syncthreads();

    // u = q0 @ Wk^T : warp per output row j
    for (int j = wid; j < HH; j += 8) {
        const float* row = Wk + (size_t)j * HH;
        float acc = 0.f;
        #pragma unroll
        for (int d = lane; d < HH; d += 32) acc = fmaf(q0[d], row[d], acc);
        #pragma unroll
        for (int o = 16; o; o >>= 1) acc += __shfl_down_sync(0xffffffffu, acc, o);
        if (lane == 0) u[j] = acc;
    }
    __syncthreads();

    // scores over all t : warp per t
    const float scale = 0.0625f;   // 1/sqrt(256)
    for (int t = wid; t < TT; t += 8) {
        const float* hr = &g_h[t][b][0];
        float acc = 0.f;
        #pragma unroll
        for (int d = lane; d < HH; d += 32) acc = fmaf(u[d], hr[d], acc);
        #pragma unroll
        for (int o = 16; o; o >>= 1) acc += __shfl_down_sync(0xffffffffu, acc, o);
        if (lane == 0) sc[t] = scale * (acc + qbk_s);
    }
    __syncthreads();

    // softmax over T=512
    {
        float s0 = sc[tid], s1 = sc[tid + 256];
        float M = block_max(fmaxf(s0, s1), red);
        float e0 = __expf(s0 - M), e1 = __expf(s1 - M);
        float S = block_sum(e0 + e1, red);
        float inv = 1.f / S;
        sc[tid] = e0 * inv;
        sc[tid + 256] = e1 * inv;
    }
    __syncthreads();

    // hbar[d] = sum_t attn[t] * h[t][b][d]
    {
        float acc = 0.f;
        #pragma unroll 4
        for (int t = 0; t < TT; ++t) acc = fmaf(sc[t], g_h[t][b][tid], acc);
        hbar[tid] = acc;
    }
    __syncthreads();

    // vb = hbar @ Wv + bv
    {
        float s = bv[tid];
        #pragma unroll 4
        for (int d = 0; d < HH; ++d) s = fmaf(hbar[d], Wv[d * HH + tid], s);
        vb[tid] = s;
    }
    __syncthreads();

    // ob = vb @ Wo + bo
    {
        float s = bo[tid];
        #pragma unroll 4
        for (int d = 0; d < HH; ++d) s = fmaf(vb[d], Wo[d * HH + tid], s);
        ob[tid] = s;
    }
    __syncthreads();

    // z = relu(ob @ W1 + b1)
    if (tid < 32) {
        float s = b1[tid];
        #pragma unroll 4
        for (int d = 0; d < HH; ++d) s = fmaf(ob[d], W1[d * 32 + tid], s);
        z[tid] = fmaxf(s, 0.f);
    }
    __syncthreads();

    // out = z @ W2 + b2
    if (tid < 3) {
        float s = b2[tid];
        #pragma unroll
        for (int d = 0; d < 32; ++d) s = fmaf(z[d], W2[d * 3 + tid], s);
        out[b * 3 + tid] = s;
    }
}

// ---------------------------------------------------------------------------
extern "C" void kernel_launch(void* const* d_in, const int* in_sizes, int n_in,
                              void* d_out, int out_size) {
    const float* x  = (const float*)d_in[0];
    const float* Wi = (const float*)d_in[1];
    const float* Wh = (const float*)d_in[2];
    const float* bg = (const float*)d_in[3];
    const float* Wq = (const float*)d_in[4];
    const float* bq = (const float*)d_in[5];
    const float* Wk = (const float*)d_in[6];
    const float* bk = (const float*)d_in[7];
    const float* Wv = (const float*)d_in[8];
    const float* bv = (const float*)d_in[9];
    const float* Wo = (const float*)d_in[10];
    const float* bo = (const float*)d_in[11];
    const float* W1 = (const float*)d_in[12];
    const float* b1 = (const float*)d_in[13];
    const float* W2 = (const float*)d_in[14];
    const float* b2 = (const float*)d_in[15];
    float* out = (float*)d_out;

    init_kernel<<<8, 256>>>();
    lstm_scan_kernel<<<NBLK, NTHR>>>(x, Wi, Wh, bg);
    attn_tail_kernel<<<BB, NTHR>>>(Wq, bq, Wk, bk, Wv, bv, Wo, bo,
                                   W1, b1, W2, b2, out);
}

// round 9
// speedup vs baseline: 5.2300x; 5.2300x over previous
#include <cuda_runtime.h>

#define BB   64
#define TT   512
#define DD   256
#define HH   256
#define G4   (4*HH)
#define NBLK 128
#define NTHR 256
#define NBG  4      // batch groups (16 batches each)
#define NUG  32     // unit groups (8 units each)
#define BPB  16     // batches per block
#define UPB  8      // units per block
#define SEGP 36     // 32-float k-segment padded to 36 (bank skew: 36%32=4)

// h after each step: g_h[t][b][unit]
__device__ float g_h[TT][BB][HH];
// per-step, per-batch-group arrival counters (target = NUG)
__device__ unsigned g_cnt[TT][NBG];

typedef unsigned long long u64;

// ---------------------------------------------------------------------------
__global__ void init_kernel() {
    int i = blockIdx.x * blockDim.x + threadIdx.x;
    if (i < TT * NBG) ((unsigned*)g_cnt)[i] = 0u;
}

// ---------------------------------------------------------------------------
__device__ __forceinline__ float sigm(float x) {
    x = fminf(fmaxf(x, -30.f), 30.f);
    return 1.0f / (1.0f + __expf(-x));
}
__device__ __forceinline__ float tanh_e(float x) {
    x = fminf(fmaxf(x, -15.f), 15.f);
    float e = __expf(2.0f * x);
    return (e - 1.0f) / (e + 1.0f);
}

// packed fp32x2 FMA (sm_103a FFMA2 — 2x fp32 throughput per issue)
__device__ __forceinline__ u64 ffma2(u64 a, u64 b, u64 c) {
    u64 d;
    asm("fma.rn.f32x2 %0, %1, %2, %3;" : "=l"(d) : "l"(a), "l"(b), "l"(c));
    return d;
}
__device__ __forceinline__ u64 pack2(float lo, float hi) {
    u64 d; asm("mov.b64 %0, {%1, %2};" : "=l"(d) : "f"(lo), "f"(hi)); return d;
}
__device__ __forceinline__ float2 unpack2(u64 v) {
    float lo, hi; asm("mov.b64 {%0, %1}, %2;" : "=f"(lo), "=f"(hi) : "l"(v));
    return make_float2(lo, hi);
}

__device__ __forceinline__ void cp16(void* smem_dst, const void* gsrc) {
    unsigned d = (unsigned)__cvta_generic_to_shared(smem_dst);
    asm volatile("cp.async.cg.shared.global [%0], [%1], 16;" :: "r"(d), "l"(gsrc));
}
__device__ __forceinline__ void cp_commit() { asm volatile("cp.async.commit_group;"); }
__device__ __forceinline__ void cp_wait0()  { asm volatile("cp.async.wait_group 0;"); }

// ---------------------------------------------------------------------------
// Persistent LSTM scan, weights-in-registers, bank-conflict-free operands.
// Block (bg, ug): batches [bg*16,+16), units [ug*8,+8) -> 32 gate columns.
// Thread tid = c*8 + ks : c = gate*8 + u (column), ks = k-segment (32 k each).
// Operand tiles stored as [batch][segment][36]: lane (c,ks) reads banks
// 4*(ks+i)+j -> all 32 banks covered once per warp access (4-way broadcast
// over the c-replicated lanes) => 1 wavefront per LDS.128.
__global__ void __launch_bounds__(NTHR, 1) lstm_scan_kernel(
    const float* __restrict__ x,   // [B,T,D]
    const float* __restrict__ Wi,  // [D,4H]
    const float* __restrict__ Wh,  // [H,4H]
    const float* __restrict__ bias)// [4H]
{
    __shared__ __align__(16) float xs[2][BPB][8][SEGP];  // 2 x 18KB
    __shared__ __align__(16) float hs[BPB][8][SEGP];     // 18KB
    __shared__ __align__(16) float ps[32][BPB];          //  2KB

    const int tid = threadIdx.x;
    const int blk = blockIdx.x;
    const int bg  = blk & (NBG - 1);
    const int ug  = blk >> 2;
    const int c   = tid >> 3;          // column 0..31
    const int ks  = tid & 7;           // k-segment 0..7
    const int gate = c >> 3, uu = c & 7;
    const int gcol = gate * HH + ug * UPB + uu;

    // ---- weights into registers (one time) ----
    u64 wi_r[16], wh_r[16];
    #pragma unroll
    for (int j = 0; j < 16; ++j) {
        int k = ks * 32 + 2 * j;
        wi_r[j] = pack2(Wi[(size_t)k * G4 + gcol], Wi[(size_t)(k + 1) * G4 + gcol]);
        wh_r[j] = pack2(Wh[(size_t)k * G4 + gcol], Wh[(size_t)(k + 1) * G4 + gcol]);
    }
    const float bias_c = bias[gcol];

    // activation-state mapping (threads < 128): one (unit, batch) each
    const int au = tid >> 4;           // unit 0..7
    const int ab = tid & 15;           // batch 0..15
    float cst = 0.f;

    // chunk mapping for 16KB tile staging: 1024 x 16B chunks, 4 per thread
    // chunk -> batch bl = chunk>>6, row-offset off = chunk&63 (off*4 floats)
    // dest segment = off>>3, within-segment 16B slot = off&7

    // ---- prologue: stage x_0 ----
    #pragma unroll
    for (int j = 0; j < 4; ++j) {
        int chunk = tid + j * NTHR;
        int bl = chunk >> 6, off = chunk & 63;
        cp16(&xs[0][bl][off >> 3][(off & 7) * 4],
             x + ((size_t)(bg * BPB + bl) * TT + 0) * DD + off * 4);
    }
    cp_commit(); cp_wait0();
    __syncthreads();

    for (int t = 0; t < TT; ++t) {
        const int cur = t & 1, nxt = cur ^ 1;

        // 1. prefetch x_{t+1} (issued now, committed with the h stage below)
        if (t + 1 < TT) {
            #pragma unroll
            for (int j = 0; j < 4; ++j) {
                int chunk = tid + j * NTHR;
                int bl = chunk >> 6, off = chunk & 63;
                cp16(&xs[nxt][bl][off >> 3][(off & 7) * 4],
                     x + ((size_t)(bg * BPB + bl) * TT + (t + 1)) * DD + off * 4);
            }
        }

        // 2. x-phase: acc[b] += x_t[b,k] * Wi[k,col]   (16 independent chains)
        u64 acc[BPB];
        #pragma unroll
        for (int b = 0; b < BPB; ++b) acc[b] = 0ull;
        #pragma unroll
        for (int b = 0; b < BPB; ++b) {
            const ulonglong2* xr = (const ulonglong2*)&xs[cur][b][ks][0];
            #pragma unroll
            for (int i = 0; i < 8; ++i) {
                ulonglong2 xv = xr[i];
                acc[b] = ffma2(wi_r[2 * i],     xv.x, acc[b]);
                acc[b] = ffma2(wi_r[2 * i + 1], xv.y, acc[b]);
            }
        }

        if (t > 0) {
            // 3. wait for all unit-groups of this batch-group at t-1
            if (tid == 0) {
                volatile unsigned* f = &g_cnt[t - 1][bg];
                while (*f < (unsigned)NUG) { }
                __threadfence();               // acquire
            }
            __syncthreads();

            // 4. stage h_{t-1} tile (16KB) + retire x prefetch
            const float* hsrc = &g_h[t - 1][bg * BPB][0];
            #pragma unroll
            for (int j = 0; j < 4; ++j) {
                int chunk = tid + j * NTHR;
                int bl = chunk >> 6, off = chunk & 63;
                cp16(&hs[bl][off >> 3][(off & 7) * 4], hsrc + chunk * 16 / 4);
            }
            cp_commit(); cp_wait0();
            __syncthreads();

            // 5. h-phase: acc[b] += h_{t-1}[b,k] * Wh[k,col]
            #pragma unroll
            for (int b = 0; b < BPB; ++b) {
                const ulonglong2* hr = (const ulonglong2*)&hs[b][ks][0];
                #pragma unroll
                for (int i = 0; i < 8; ++i) {
                    ulonglong2 hv = hr[i];
                    acc[b] = ffma2(wh_r[2 * i],     hv.x, acc[b]);
                    acc[b] = ffma2(wh_r[2 * i + 1], hv.y, acc[b]);
                }
            }
        } else {
            cp_commit(); cp_wait0();           // retire x_1 prefetch group
            __syncthreads();
        }

        // 6. reduce over the 8 k-segments (8 consecutive lanes share a column)
        float4 s[4];
        #pragma unroll
        for (int q = 0; q < BPB; ++q) {
            float2 p = unpack2(acc[q]);
            float v = p.x + p.y;
            v += __shfl_xor_sync(0xffffffffu, v, 1);
            v += __shfl_xor_sync(0xffffffffu, v, 2);
            v += __shfl_xor_sync(0xffffffffu, v, 4);
            ((float*)s)[q] = v + bias_c;
        }
        if (ks == 0) {
            float4* pr = (float4*)&ps[c][0];
            pr[0] = s[0]; pr[1] = s[1]; pr[2] = s[2]; pr[3] = s[3];
        }
        __syncthreads();

        // 7. activations: thread (u, b) owns one cell state
        if (tid < 128) {
            float gi = ps[     au][ab];
            float gf = ps[ 8 + au][ab];
            float gg = ps[16 + au][ab];
            float go = ps[24 + au][ab];
            cst = sigm(gf) * cst + sigm(gi) * tanh_e(gg);
            float hv = sigm(go) * tanh_e(cst);
            g_h[t][bg * BPB + ab][ug * UPB + au] = hv;
        }
        __syncthreads();

        // 8. publish
        if (tid == 0) {
            __threadfence();                   // release
            atomicAdd(&g_cnt[t][bg], 1u);
        }
    }
}

// ---------------------------------------------------------------------------
// block-level reductions (256 threads)
__device__ __forceinline__ float block_sum(float v, volatile float* red) {
    int lane = threadIdx.x & 31, wid = threadIdx.x >> 5;
    #pragma unroll
    for (int o = 16; o; o >>= 1) v += __shfl_down_sync(0xffffffffu, v, o);
    if (lane == 0) red[wid] = v;
    __syncthreads();
    if (threadIdx.x == 0) {
        float s = 0.f;
        #pragma unroll
        for (int i = 0; i < 8; ++i) s += red[i];
        red[0] = s;
    }
    __syncthreads();
    float r = red[0];
    __syncthreads();
    return r;
}
__device__ __forceinline__ float block_max(float v, volatile float* red) {
    int lane = threadIdx.x & 31, wid = threadIdx.x >> 5;
    #pragma unroll
    for (int o = 16; o; o >>= 1) v = fmaxf(v, __shfl_down_sync(0xffffffffu, v, o));
    if (lane == 0) red[wid] = v;
    __syncthreads();
    if (threadIdx.x == 0) {
        float s = red[0];
        #pragma unroll
        for (int i = 1; i < 8; ++i) s = fmaxf(s, red[i]);
        red[0] = s;
    }
    __syncthreads();
    float r = red[0];
    __syncthreads();
    return r;
}

// ---------------------------------------------------------------------------
// Attention + MLP tail. One block per batch element.
//   scores_t = scale*((q0 Wk^T)·h_t + q0·bk) ; o0 = (Σ attn_t h_t) Wv + bv
__global__ void __launch_bounds__(NTHR) attn_tail_kernel(
    const float* __restrict__ Wq, const float* __restrict__ bq,
    const float* __restrict__ Wk, const float* __restrict__ bk,
    const float* __restrict__ Wv, const float* __restrict__ bv,
    const float* __restrict__ Wo, const float* __restrict__ bo,
    const float* __restrict__ W1, const float* __restrict__ b1,
    const float* __restrict__ W2, const float* __restrict__ b2,
    float* __restrict__ out)
{
    __shared__ float h0[HH], q0[HH], u[HH], hbar[HH], vb[HH], ob[HH];
    __shared__ float sc[TT];
    __shared__ float z[32];
    __shared__ float red[8];
    __shared__ float qbk_s;

    const int b = blockIdx.x;
    const int tid = threadIdx.x;
    const int lane = tid & 31, wid = tid >> 5;

    h0[tid] = g_h[0][b][tid];
    __syncthreads();

    // q0 = h0 @ Wq + bq
    {
        float s = bq[tid];
        #pragma unroll 4
        for (int d = 0; d < HH; ++d) s = fmaf(h0[d], Wq[d * HH + tid], s);
        q0[tid] = s;
    }
    __syncthreads();

    // qbk = q0 . bk
    {
        float p = q0[tid] * bk[tid];
        float s = block_sum(p, red);
        if (tid == 0) qbk_s = s;
    }
    __syncthreads();

    // u = q0 @ Wk^T : warp per output row j
    for (int j = wid; j < HH; j += 8) {
        const float* row = Wk + (size_t)j * HH;
        float acc = 0.f;
        #pragma unroll
        for (int d = lane; d < HH; d += 32) acc = fmaf(q0[d], row[d], acc);
        #pragma unroll
        for (int o = 16; o; o >>= 1) acc += __shfl_down_sync(0xffffffffu, acc, o);
        if (lane == 0) u[j] = acc;
    }
    __syncthreads();

    // scores over all t : warp per t
    const float scale = 0.0625f;   // 1/sqrt(256)
    for (int t = wid; t < TT; t += 8) {
        const float* hr = &g_h[t][b][0];
        float acc = 0.f;
        #pragma unroll
        for (int d = lane; d < HH; d += 32) acc = fmaf(u[d], hr[d], acc);
        #pragma unroll
        for (int o = 16; o; o >>= 1) acc += __shfl_down_sync(0xffffffffu, acc, o);
        if (lane == 0) sc[t] = scale * (acc + qbk_s);
    }
    __syncthreads();

    // softmax over T=512
    {
        float s0 = sc[tid], s1 = sc[tid + 256];
        float M = block_max(fmaxf(s0, s1), red);
        float e0 = __expf(s0 - M), e1 = __expf(s1 - M);
        float S = block_sum(e0 + e1, red);
        float inv = 1.f / S;
        sc[tid] = e0 * inv;
        sc[tid + 256] = e1 * inv;
    }
    __syncthreads();

    // hbar[d] = sum_t attn[t] * h[t][b][d]
    {
        float acc = 0.f;
        #pragma unroll 4
        for (int t = 0; t < TT; ++t) acc = fmaf(sc[t], g_h[t][b][tid], acc);
        hbar[tid] = acc;
    }
    __syncthreads();

    // vb = hbar @ Wv + bv
    {
        float s = bv[tid];
        #pragma unroll 4
        for (int d = 0; d < HH; ++d) s = fmaf(hbar[d], Wv[d * HH + tid], s);
        vb[tid] = s;
    }
    __syncthreads();

    // ob = vb @ Wo + bo
    {
        float s = bo[tid];
        #pragma unroll 4
        for (int d = 0; d < HH; ++d) s = fmaf(vb[d], Wo[d * HH + tid], s);
        ob[tid] = s;
    }
    __syncthreads();

    // z = relu(ob @ W1 + b1)
    if (tid < 32) {
        float s = b1[tid];
        #pragma unroll 4
        for (int d = 0; d < HH; ++d) s = fmaf(ob[d], W1[d * 32 + tid], s);
        z[tid] = fmaxf(s, 0.f);
    }
    __syncthreads();

    // out = z @ W2 + b2
    if (tid < 3) {
        float s = b2[tid];
        #pragma unroll
        for (int d = 0; d < 32; ++d) s = fmaf(z[d], W2[d * 3 + tid], s);
        out[b * 3 + tid] = s;
    }
}

// ---------------------------------------------------------------------------
extern "C" void kernel_launch(void* const* d_in, const int* in_sizes, int n_in,
                              void* d_out, int out_size) {
    const float* x  = (const float*)d_in[0];
    const float* Wi = (const float*)d_in[1];
    const float* Wh = (const float*)d_in[2];
    const float* bg = (const float*)d_in[3];
    const float* Wq = (const float*)d_in[4];
    const float* bq = (const float*)d_in[5];
    const float* Wk = (const float*)d_in[6];
    const float* bk = (const float*)d_in[7];
    const float* Wv = (const float*)d_in[8];
    const float* bv = (const float*)d_in[9];
    const float* Wo = (const float*)d_in[10];
    const float* bo = (const float*)d_in[11];
    const float* W1 = (const float*)d_in[12];
    const float* b1 = (const float*)d_in[13];
    const float* W2 = (const float*)d_in[14];
    const float* b2 = (const float*)d_in[15];
    float* out = (float*)d_out;

    init_kernel<<<8, 256>>>();
    lstm_scan_kernel<<<NBLK, NTHR>>>(x, Wi, Wh, bg);
    attn_tail_kernel<<<BB, NTHR>>>(Wq, bq, Wk, bk, Wv, bv, Wo, bo,
                                   W1, b1, W2, b2, out);
}

// round 10
// speedup vs baseline: 5.2358x; 1.0011x over previous
#include <cuda_runtime.h>

#define BB   64
#define TT   512
#define DD   256
#define HH   256
#define G4   (4*HH)
#define NBLK 128
#define NTHR 256
#define NBG  4      // batch groups (16 batches each)
#define NUG  32     // unit groups (8 units each)
#define BPB  16     // batches per block
#define UPB  8      // units per block
#define SEGP 36     // 32-float k-segment padded to 36 (bank skew: 36%32=4)

// h after each step: g_h[t][b][unit]
__device__ float g_h[TT][BB][HH];
// per-step, per-batch-group arrival counters (target = NUG)
__device__ unsigned g_cnt[TT][NBG];

typedef unsigned long long u64;

// ---------------------------------------------------------------------------
__global__ void init_kernel() {
    int i = blockIdx.x * blockDim.x + threadIdx.x;
    if (i < TT * NBG) ((unsigned*)g_cnt)[i] = 0u;
}

// ---------------------------------------------------------------------------
__device__ __forceinline__ float sigm(float x) {
    x = fminf(fmaxf(x, -30.f), 30.f);
    return 1.0f / (1.0f + __expf(-x));
}
__device__ __forceinline__ float tanh_e(float x) {
    x = fminf(fmaxf(x, -15.f), 15.f);
    float e = __expf(2.0f * x);
    return (e - 1.0f) / (e + 1.0f);
}

// packed fp32x2 FMA (sm_103a FFMA2 — 2x fp32 throughput per issue)
__device__ __forceinline__ u64 ffma2(u64 a, u64 b, u64 c) {
    u64 d;
    asm("fma.rn.f32x2 %0, %1, %2, %3;" : "=l"(d) : "l"(a), "l"(b), "l"(c));
    return d;
}
__device__ __forceinline__ u64 pack2(float lo, float hi) {
    u64 d; asm("mov.b64 %0, {%1, %2};" : "=l"(d) : "f"(lo), "f"(hi)); return d;
}
__device__ __forceinline__ float2 unpack2(u64 v) {
    float lo, hi; asm("mov.b64 {%0, %1}, %2;" : "=f"(lo), "=f"(hi) : "l"(v));
    return make_float2(lo, hi);
}

__device__ __forceinline__ void cp16(void* smem_dst, const void* gsrc) {
    unsigned d = (unsigned)__cvta_generic_to_shared(smem_dst);
    asm volatile("cp.async.cg.shared.global [%0], [%1], 16;" :: "r"(d), "l"(gsrc));
}
__device__ __forceinline__ void cp_commit() { asm volatile("cp.async.commit_group;"); }
__device__ __forceinline__ void cp_wait0()  { asm volatile("cp.async.wait_group 0;"); }

// ---------------------------------------------------------------------------
// Persistent LSTM scan, weights-in-registers, bank-conflict-free operands.
// Block (bg, ug): batches [bg*16,+16), units [ug*8,+8) -> 32 gate columns.
// Thread tid = c*8 + ks : c = gate*8 + u (column), ks = k-segment (32 k each).
// Operand tiles stored as [batch][segment][36]: lane (c,ks) reads banks
// 4*(ks+i)+j -> all 32 banks covered once per warp access (4-way broadcast
// over the c-replicated lanes) => 1 wavefront per LDS.128.
__global__ void __launch_bounds__(NTHR, 1) lstm_scan_kernel(
    const float* __restrict__ x,   // [B,T,D]
    const float* __restrict__ Wi,  // [D,4H]
    const float* __restrict__ Wh,  // [H,4H]
    const float* __restrict__ bias)// [4H]
{
    __shared__ __align__(16) float xs[2][BPB][8][SEGP];  // 2 x 18KB
    __shared__ __align__(16) float hs[BPB][8][SEGP];     // 18KB
    __shared__ __align__(16) float ps[32][BPB];          //  2KB

    const int tid = threadIdx.x;
    const int blk = blockIdx.x;
    const int bg  = blk & (NBG - 1);
    const int ug  = blk >> 2;
    const int c   = tid >> 3;          // column 0..31
    const int ks  = tid & 7;           // k-segment 0..7
    const int gate = c >> 3, uu = c & 7;
    const int gcol = gate * HH + ug * UPB + uu;

    // ---- weights into registers (one time) ----
    u64 wi_r[16], wh_r[16];
    #pragma unroll
    for (int j = 0; j < 16; ++j) {
        int k = ks * 32 + 2 * j;
        wi_r[j] = pack2(Wi[(size_t)k * G4 + gcol], Wi[(size_t)(k + 1) * G4 + gcol]);
        wh_r[j] = pack2(Wh[(size_t)k * G4 + gcol], Wh[(size_t)(k + 1) * G4 + gcol]);
    }
    const float bias_c = bias[gcol];

    // activation-state mapping (threads < 128): one (unit, batch) each
    const int au = tid >> 4;           // unit 0..7
    const int ab = tid & 15;           // batch 0..15
    float cst = 0.f;

    // chunk mapping for 16KB tile staging: 1024 x 16B chunks, 4 per thread
    // chunk -> batch bl = chunk>>6, row-offset off = chunk&63 (off*4 floats)
    // dest segment = off>>3, within-segment 16B slot = off&7

    // ---- prologue: stage x_0 ----
    #pragma unroll
    for (int j = 0; j < 4; ++j) {
        int chunk = tid + j * NTHR;
        int bl = chunk >> 6, off = chunk & 63;
        cp16(&xs[0][bl][off >> 3][(off & 7) * 4],
             x + ((size_t)(bg * BPB + bl) * TT + 0) * DD + off * 4);
    }
    cp_commit(); cp_wait0();
    __syncthreads();

    for (int t = 0; t < TT; ++t) {
        const int cur = t & 1, nxt = cur ^ 1;

        // 1. prefetch x_{t+1} (issued now, committed with the h stage below)
        if (t + 1 < TT) {
            #pragma unroll
            for (int j = 0; j < 4; ++j) {
                int chunk = tid + j * NTHR;
                int bl = chunk >> 6, off = chunk & 63;
                cp16(&xs[nxt][bl][off >> 3][(off & 7) * 4],
                     x + ((size_t)(bg * BPB + bl) * TT + (t + 1)) * DD + off * 4);
            }
        }

        // 2. x-phase: acc[b] += x_t[b,k] * Wi[k,col]   (16 independent chains)
        u64 acc[BPB];
        #pragma unroll
        for (int b = 0; b < BPB; ++b) acc[b] = 0ull;
        #pragma unroll
        for (int b = 0; b < BPB; ++b) {
            const ulonglong2* xr = (const ulonglong2*)&xs[cur][b][ks][0];
            #pragma unroll
            for (int i = 0; i < 8; ++i) {
                ulonglong2 xv = xr[i];
                acc[b] = ffma2(wi_r[2 * i],     xv.x, acc[b]);
                acc[b] = ffma2(wi_r[2 * i + 1], xv.y, acc[b]);
            }
        }

        if (t > 0) {
            // 3. wait for all unit-groups of this batch-group at t-1
            if (tid == 0) {
                volatile unsigned* f = &g_cnt[t - 1][bg];
                while (*f < (unsigned)NUG) { }
                __threadfence();               // acquire
            }
            __syncthreads();

            // 4. stage h_{t-1} tile (16KB) + retire x prefetch
            const float* hsrc = &g_h[t - 1][bg * BPB][0];
            #pragma unroll
            for (int j = 0; j < 4; ++j) {
                int chunk = tid + j * NTHR;
                int bl = chunk >> 6, off = chunk & 63;
                cp16(&hs[bl][off >> 3][(off & 7) * 4], hsrc + chunk * 16 / 4);
            }
            cp_commit(); cp_wait0();
            __syncthreads();

            // 5. h-phase: acc[b] += h_{t-1}[b,k] * Wh[k,col]
            #pragma unroll
            for (int b = 0; b < BPB; ++b) {
                const ulonglong2* hr = (const ulonglong2*)&hs[b][ks][0];
                #pragma unroll
                for (int i = 0; i < 8; ++i) {
                    ulonglong2 hv = hr[i];
                    acc[b] = ffma2(wh_r[2 * i],     hv.x, acc[b]);
                    acc[b] = ffma2(wh_r[2 * i + 1], hv.y, acc[b]);
                }
            }
        } else {
            cp_commit(); cp_wait0();           // retire x_1 prefetch group
            __syncthreads();
        }

        // 6. reduce over the 8 k-segments (8 consecutive lanes share a column)
        float4 s[4];
        #pragma unroll
        for (int q = 0; q < BPB; ++q) {
            float2 p = unpack2(acc[q]);
            float v = p.x + p.y;
            v += __shfl_xor_sync(0xffffffffu, v, 1);
            v += __shfl_xor_sync(0xffffffffu, v, 2);
            v += __shfl_xor_sync(0xffffffffu, v, 4);
            ((float*)s)[q] = v + bias_c;
        }
        if (ks == 0) {
            float4* pr = (float4*)&ps[c][0];
            pr[0] = s[0]; pr[1] = s[1]; pr[2] = s[2]; pr[3] = s[3];
        }
        __syncthreads();

        // 7. activations: thread (u, b) owns one cell state
        if (tid < 128) {
            float gi = ps[     au][ab];
            float gf = ps[ 8 + au][ab];
            float gg = ps[16 + au][ab];
            float go = ps[24 + au][ab];
            cst = sigm(gf) * cst + sigm(gi) * tanh_e(gg);
            float hv = sigm(go) * tanh_e(cst);
            g_h[t][bg * BPB + ab][ug * UPB + au] = hv;
        }
        __syncthreads();

        // 8. publish
        if (tid == 0) {
            __threadfence();                   // release
            atomicAdd(&g_cnt[t][bg], 1u);
        }
    }
}

// ---------------------------------------------------------------------------
// block-level reductions (256 threads)
__device__ __forceinline__ float block_sum(float v, volatile float* red) {
    int lane = threadIdx.x & 31, wid = threadIdx.x >> 5;
    #pragma unroll
    for (int o = 16; o; o >>= 1) v += __shfl_down_sync(0xffffffffu, v, o);
    if (lane == 0) red[wid] = v;
    __syncthreads();
    if (threadIdx.x == 0) {
        float s = 0.f;
        #pragma unroll
        for (int i = 0; i < 8; ++i) s += red[i];
        red[0] = s;
    }
    __syncthreads();
    float r = red[0];
    __syncthreads();
    return r;
}
__device__ __forceinline__ float block_max(float v, volatile float* red) {
    int lane = threadIdx.x & 31, wid = threadIdx.x >> 5;
    #pragma unroll
    for (int o = 16; o; o >>= 1) v = fmaxf(v, __shfl_down_sync(0xffffffffu, v, o));
    if (lane == 0) red[wid] = v;
    __syncthreads();
    if (threadIdx.x == 0) {
        float s = red[0];
        #pragma unroll
        for (int i = 1; i < 8; ++i) s = fmaxf(s, red[i]);
        red[0] = s;
    }
    __syncthreads();
    float r = red[0];
    __syncthreads();
    return r;
}

// ---------------------------------------------------------------------------
// Attention + MLP tail. One block per batch element.
//   scores_t = scale*((q0 Wk^T)·h_t + q0·bk) ; o0 = (Σ attn_t h_t) Wv + bv
__global__ void __launch_bounds__(NTHR) attn_tail_kernel(
    const float* __restrict__ Wq, const float* __restrict__ bq,
    const float* __restrict__ Wk, const float* __restrict__ bk,
    const float* __restrict__ Wv, const float* __restrict__ bv,
    const float* __restrict__ Wo, const float* __restrict__ bo,
    const float* __restrict__ W1, const float* __restrict__ b1,
    const float* __restrict__ W2, const float* __restrict__ b2,
    float* __restrict__ out)
{
    __shared__ float h0[HH], q0[HH], u[HH], hbar[HH], vb[HH], ob[HH];
    __shared__ float sc[TT];
    __shared__ float z[32];
    __shared__ float red[8];
    __shared__ float qbk_s;

    const int b = blockIdx.x;
    const int tid = threadIdx.x;
    const int lane = tid & 31, wid = tid >> 5;

    h0[tid] = g_h[0][b][tid];
    __syncthreads();

    // q0 = h0 @ Wq + bq
    {
        float s = bq[tid];
        #pragma unroll 4
        for (int d = 0; d < HH; ++d) s = fmaf(h0[d], Wq[d * HH + tid], s);
        q0[tid] = s;
    }
    __syncthreads();

    // qbk = q0 . bk
    {
        float p = q0[tid] * bk[tid];
        float s = block_sum(p, red);
        if (tid == 0) qbk_s = s;
    }
    __syncthreads();

    // u = q0 @ Wk^T : warp per output row j
    for (int j = wid; j < HH; j += 8) {
        const float* row = Wk + (size_t)j * HH;
        float acc = 0.f;
        #pragma unroll
        for (int d = lane; d < HH; d += 32) acc = fmaf(q0[d], row[d], acc);
        #pragma unroll
        for (int o = 16; o; o >>= 1) acc += __shfl_down_sync(0xffffffffu, acc, o);
        if (lane == 0) u[j] = acc;
    }
    __syncthreads();

    // scores over all t : warp per t
    const float scale = 0.0625f;   // 1/sqrt(256)
    for (int t = wid; t < TT; t += 8) {
        const float* hr = &g_h[t][b][0];
        float acc = 0.f;
        #pragma unroll
        for (int d = lane; d < HH; d += 32) acc = fmaf(u[d], hr[d], acc);
        #pragma unroll
        for (int o = 16; o; o >>= 1) acc += __shfl_down_sync(0xffffffffu, acc, o);
        if (lane == 0) sc[t] = scale * (acc + qbk_s);
    }
    __syncthreads();

    // softmax over T=512
    {
        float s0 = sc[tid], s1 = sc[tid + 256];
        float M = block_max(fmaxf(s0, s1), red);
        float e0 = __expf(s0 - M), e1 = __expf(s1 - M);
        float S = block_sum(e0 + e1, red);
        float inv = 1.f / S;
        sc[tid] = e0 * inv;
        sc[tid + 256] = e1 * inv;
    }
    __syncthreads();

    // hbar[d] = sum_t attn[t] * h[t][b][d]
    {
        float acc = 0.f;
        #pragma unroll 4
        for (int t = 0; t < TT; ++t) acc = fmaf(sc[t], g_h[t][b][tid], acc);
        hbar[tid] = acc;
    }
    __syncthreads();

    // vb = hbar @ Wv + bv
    {
        float s = bv[tid];
        #pragma unroll 4
        for (int d = 0; d < HH; ++d) s = fmaf(hbar[d], Wv[d * HH + tid], s);
        vb[tid] = s;
    }
    __syncthreads();

    // ob = vb @ Wo + bo
    {
        float s = bo[tid];
        #pragma unroll 4
        for (int d = 0; d < HH; ++d) s = fmaf(vb[d], Wo[d * HH + tid], s);
        ob[tid] = s;
    }
    __syncthreads();

    // z = relu(ob @ W1 + b1)
    if (tid < 32) {
        float s = b1[tid];
        #pragma unroll 4
        for (int d = 0; d < HH; ++d) s = fmaf(ob[d], W1[d * 32 + tid], s);
        z[tid] = fmaxf(s, 0.f);
    }
    __syncthreads();

    // out = z @ W2 + b2
    if (tid < 3) {
        float s = b2[tid];
        #pragma unroll
        for (int d = 0; d < 32; ++d) s = fmaf(z[d], W2[d * 3 + tid], s);
        out[b * 3 + tid] = s;
    }
}

// ---------------------------------------------------------------------------
extern "C" void kernel_launch(void* const* d_in, const int* in_sizes, int n_in,
                              void* d_out, int out_size) {
    const float* x  = (const float*)d_in[0];
    const float* Wi = (const float*)d_in[1];
    const float* Wh = (const float*)d_in[2];
    const float* bg = (const float*)d_in[3];
    const float* Wq = (const float*)d_in[4];
    const float* bq = (const float*)d_in[5];
    const float* Wk = (const float*)d_in[6];
    const float* bk = (const float*)d_in[7];
    const float* Wv = (const float*)d_in[8];
    const float* bv = (const float*)d_in[9];
    const float* Wo = (const float*)d_in[10];
    const float* bo = (const float*)d_in[11];
    const float* W1 = (const float*)d_in[12];
    const float* b1 = (const float*)d_in[13];
    const float* W2 = (const float*)d_in[14];
    const float* b2 = (const float*)d_in[15];
    float* out = (float*)d_out;

    init_kernel<<<8, 256>>>();
    lstm_scan_kernel<<<NBLK, NTHR>>>(x, Wi, Wh, bg);
    attn_tail_kernel<<<BB, NTHR>>>(Wq, bq, Wk, bk, Wv, bv, Wo, bo,
                                   W1, b1, W2, b2, out);
}